// round 1
// baseline (speedup 1.0000x reference)
#include <cuda_runtime.h>
#include <cstdint>

// Problem dims (fixed by the reference generator)
#define Hh 56
#define Ww 56
#define HO 58
#define WO 58
#define PLANE_IN  (Hh * Ww)    // 3136
#define PLANE_OUT (HO * WO)    // 3364

__global__ void __launch_bounds__(256)
weight_pad2d_kernel(const float* __restrict__ x,
                    const float* __restrict__ topW,
                    const float* __restrict__ botW,
                    const float* __restrict__ leftW,
                    const float* __restrict__ rightW,
                    const float* __restrict__ topleftW,
                    const float* __restrict__ toprightW,
                    const float* __restrict__ botleftW,
                    const float* __restrict__ botrightW,
                    const int* __restrict__ num_patches_ptr,
                    int C,
                    float* __restrict__ out)
{
    const int plane = blockIdx.x;        // b * C + ch
    const int bidx  = plane / C;
    const int ch    = plane - bidx * C;

    const int P  = *num_patches_ptr;     // device scalar, L2-cached
    const int PP = P * P;
    const int within = bidx % PP;
    const bool topz   = within < P;
    const bool botz   = within >= PP - P;
    const bool leftz  = (bidx % P) == 0;
    const bool rightz = (bidx % P) == (P - 1);

    const float wT  = topW[ch];
    const float wB  = botW[ch];
    const float wL  = leftW[ch];
    const float wR  = rightW[ch];
    const float wTL = topleftW[ch];
    const float wTR = toprightW[ch];
    const float wBL = botleftW[ch];
    const float wBR = botrightW[ch];

    const float* __restrict__ xp = x   + (size_t)plane * PLANE_IN;
    float*       __restrict__ op = out + (size_t)plane * PLANE_OUT;

    for (int i = threadIdx.x; i < PLANE_OUT; i += 256) {
        const int r = i / WO;
        const int c = i - r * WO;
        float v;
        if (r == 0) {
            if (topz) {
                v = 0.0f;
            } else if (c == 0) {
                v = leftz ? 0.0f : wTL * xp[0];
            } else if (c == WO - 1) {
                v = rightz ? 0.0f : wTR * xp[Ww - 1];
            } else {
                v = wT * (xp[c - 1] + xp[Ww + c - 1]);
            }
        } else if (r == HO - 1) {
            const float* xr2 = xp + (Hh - 2) * Ww;   // row H-2
            const float* xr1 = xp + (Hh - 1) * Ww;   // row H-1
            if (botz) {
                v = 0.0f;
            } else if (c == 0) {
                v = leftz ? 0.0f : wBL * xr1[0];
            } else if (c == WO - 1) {
                v = rightz ? 0.0f : wBR * xr1[Ww - 1];
            } else {
                v = wB * (xr2[c - 1] + xr1[c - 1]);
            }
        } else {
            const float* xr = xp + (r - 1) * Ww;
            if (c == 0) {
                v = leftz ? 0.0f : wL * (xr[0] + xr[1]);
            } else if (c == WO - 1) {
                v = rightz ? 0.0f : wR * (xr[Ww - 2] + xr[Ww - 1]);
            } else {
                v = xr[c - 1];
            }
        }
        op[i] = v;
    }
}

extern "C" void kernel_launch(void* const* d_in, const int* in_sizes, int n_in,
                              void* d_out, int out_size)
{
    const float* x         = (const float*)d_in[0];
    const float* topW      = (const float*)d_in[1];
    const float* botW      = (const float*)d_in[2];
    const float* leftW     = (const float*)d_in[3];
    const float* rightW    = (const float*)d_in[4];
    const float* topleftW  = (const float*)d_in[5];
    const float* toprightW = (const float*)d_in[6];
    const float* botleftW  = (const float*)d_in[7];
    const float* botrightW = (const float*)d_in[8];
    const int*   num_patches = (const int*)d_in[10];

    const int C = in_sizes[1];                   // 128
    const int planes = in_sizes[0] / PLANE_IN;   // b * C = 16384

    weight_pad2d_kernel<<<planes, 256>>>(
        x, topW, botW, leftW, rightW,
        topleftW, toprightW, botleftW, botrightW,
        num_patches, C, (float*)d_out);
}

// round 2
// speedup vs baseline: 1.0736x; 1.0736x over previous
#include <cuda_runtime.h>
#include <cstdint>

// Fixed problem dims
#define Hh 56
#define Ww 56
#define HO 58
#define WO 58
#define PLANE_IN  3136   // 56*56
#define PLANE_OUT 3364   // 58*58

__global__ void __launch_bounds__(256)
weight_pad2d_kernel(const float* __restrict__ x,
                    const float* __restrict__ topW,
                    const float* __restrict__ botW,
                    const float* __restrict__ leftW,
                    const float* __restrict__ rightW,
                    const float* __restrict__ topleftW,
                    const float* __restrict__ toprightW,
                    const float* __restrict__ botleftW,
                    const float* __restrict__ botrightW,
                    const int* __restrict__ num_patches_ptr,
                    int C,
                    float* __restrict__ out)
{
    const int plane = blockIdx.x;        // b * C + ch
    const int bidx  = plane / C;
    const int ch    = plane - bidx * C;

    const int P  = *num_patches_ptr;
    const int PP = P * P;
    const int within = bidx % PP;
    const bool topz   = within < P;
    const bool botz   = within >= PP - P;
    const bool leftz  = (bidx % P) == 0;
    const bool rightz = (bidx % P) == (P - 1);

    const int pair = threadIdx.x >> 6;   // 0..3 : row group
    const int c    = threadIdx.x & 63;   // lane-in-group = output column
    const bool active = (c < WO);

    const float* __restrict__ xp = x   + (size_t)plane * PLANE_IN;
    float*       __restrict__ op = out + (size_t)plane * PLANE_OUT;

    // ---- peeled top row (r = 0), handled by group 0 ----
    if (pair == 0 && active) {
        float v;
        if (c == 0) {
            v = (topz || leftz) ? 0.0f : topleftW[ch] * xp[0];
        } else if (c == WO - 1) {
            v = (topz || rightz) ? 0.0f : toprightW[ch] * xp[Ww - 1];
        } else {
            v = topz ? 0.0f : topW[ch] * (xp[c - 1] + xp[Ww + c - 1]);
        }
        op[c] = v;
    }

    // ---- peeled bottom row (r = 57), handled by group 1 ----
    if (pair == 1 && active) {
        const float* x54 = xp + (Hh - 2) * Ww;
        const float* x55 = xp + (Hh - 1) * Ww;
        float v;
        if (c == 0) {
            v = (botz || leftz) ? 0.0f : botleftW[ch] * x55[0];
        } else if (c == WO - 1) {
            v = (botz || rightz) ? 0.0f : botrightW[ch] * x55[Ww - 1];
        } else {
            v = botz ? 0.0f : botW[ch] * (x54[c - 1] + x55[c - 1]);
        }
        op[(HO - 1) * WO + c] = v;
    }

    if (!active) return;

    // ---- interior rows r = 1..56 ----
    // group 0: 4,8,...,56   group 1: 1,5,...,53   group 2: 2,...,54   group 3: 3,...,55
    const float wL = leftW[ch];
    const float wR = rightW[ch];

    const int r0 = (pair == 0) ? 4 : pair;

    #pragma unroll 4
    for (int r = r0; r < HO - 1; r += 4) {
        const float* __restrict__ xr = xp + (r - 1) * Ww;
        float v;
        if (c == 0) {
            v = leftz ? 0.0f : wL * (xr[0] + xr[1]);
        } else if (c == WO - 1) {
            v = rightz ? 0.0f : wR * (xr[Ww - 2] + xr[Ww - 1]);
        } else {
            v = xr[c - 1];
        }
        op[r * WO + c] = v;
    }
}

extern "C" void kernel_launch(void* const* d_in, const int* in_sizes, int n_in,
                              void* d_out, int out_size)
{
    const float* x         = (const float*)d_in[0];
    const float* topW      = (const float*)d_in[1];
    const float* botW      = (const float*)d_in[2];
    const float* leftW     = (const float*)d_in[3];
    const float* rightW    = (const float*)d_in[4];
    const float* topleftW  = (const float*)d_in[5];
    const float* toprightW = (const float*)d_in[6];
    const float* botleftW  = (const float*)d_in[7];
    const float* botrightW = (const float*)d_in[8];
    const int*   num_patches = (const int*)d_in[10];

    const int C = in_sizes[1];                   // 128
    const int planes = in_sizes[0] / PLANE_IN;   // b * C = 16384

    weight_pad2d_kernel<<<planes, 256>>>(
        x, topW, botW, leftW, rightW,
        topleftW, toprightW, botleftW, botrightW,
        num_patches, C, (float*)d_out);
}

// round 3
// speedup vs baseline: 1.6236x; 1.5123x over previous
#include <cuda_runtime.h>
#include <cstdint>

#define Hh 56
#define Ww 56
#define HO 58
#define WO 58
#define PLANE_IN  3136   // 56*56
#define PLANE_OUT 3364   // 58*58

__global__ void __launch_bounds__(256)
weight_pad2d_kernel(const float* __restrict__ x,
                    const float* __restrict__ topW,
                    const float* __restrict__ botW,
                    const float* __restrict__ leftW,
                    const float* __restrict__ rightW,
                    const float* __restrict__ topleftW,
                    const float* __restrict__ toprightW,
                    const float* __restrict__ botleftW,
                    const float* __restrict__ botrightW,
                    const int* __restrict__ num_patches_ptr,
                    int C,
                    float* __restrict__ out)
{
    const int plane = blockIdx.x;        // b * C + ch
    const int bidx  = plane / C;
    const int ch    = plane - bidx * C;

    const int P  = *num_patches_ptr;
    const int PP = P * P;
    const int within = bidx % PP;
    const bool topz   = within < P;
    const bool botz   = within >= PP - P;
    const bool leftz  = (bidx % P) == 0;
    const bool rightz = (bidx % P) == (P - 1);

    const int tid  = threadIdx.x;
    const int warp = tid >> 5;           // 0..7
    const int lane = tid & 31;

    const float* __restrict__ xp = x   + (size_t)plane * PLANE_IN;
    float*       __restrict__ op = out + (size_t)plane * PLANE_OUT;

    // ---- peeled top row (r=0): threads 0..63 scalar ----
    if (tid < 64) {
        const int c = tid;
        if (c < WO) {
            float v;
            if (c == 0) {
                v = (topz || leftz) ? 0.0f : topleftW[ch] * xp[0];
            } else if (c == WO - 1) {
                v = (topz || rightz) ? 0.0f : toprightW[ch] * xp[Ww - 1];
            } else {
                v = topz ? 0.0f : topW[ch] * (xp[c - 1] + xp[Ww + c - 1]);
            }
            op[c] = v;
        }
    } else if (tid < 128) {
        // ---- peeled bottom row (r=57): threads 64..127 scalar ----
        const int c = tid - 64;
        if (c < WO) {
            const float* x54 = xp + (Hh - 2) * Ww;
            const float* x55 = xp + (Hh - 1) * Ww;
            float v;
            if (c == 0) {
                v = (botz || leftz) ? 0.0f : botleftW[ch] * x55[0];
            } else if (c == WO - 1) {
                v = (botz || rightz) ? 0.0f : botrightW[ch] * x55[Ww - 1];
            } else {
                v = botz ? 0.0f : botW[ch] * (x54[c - 1] + x55[c - 1]);
            }
            op[(HO - 1) * WO + c] = v;
        }
    }

    // ---- interior rows r = 1..56: one warp per row, float2 everywhere ----
    const float wLr = leftz  ? 0.0f : leftW[ch];
    const float wRr = rightz ? 0.0f : rightW[ch];

    const bool ld = (lane < 28);   // lanes 0..27 load
    const bool st = (lane < 29);   // lanes 0..28 store

    // warp w handles rows 1+w, 9+w, ..., 49+w  (7 rows)
    #pragma unroll
    for (int k = 0; k < 7; k++) {
        const int r  = 1 + warp + 8 * k;
        const int ir = r - 1;
        float2 g = make_float2(0.0f, 0.0f);
        if (ld) g = *(const float2*)(xp + ir * Ww + 2 * lane);

        const float upx = __shfl_up_sync(0xffffffffu, g.x, 1);
        const float upy = __shfl_up_sync(0xffffffffu, g.y, 1);

        if (st) {
            const float o_lo = (lane == 0)  ? wLr * (g.x + g.y)  : upy;
            const float o_hi = (lane == 28) ? wRr * (upx + upy)  : g.x;
            *(float2*)(op + r * WO + 2 * lane) = make_float2(o_lo, o_hi);
        }
    }
}

extern "C" void kernel_launch(void* const* d_in, const int* in_sizes, int n_in,
                              void* d_out, int out_size)
{
    const float* x         = (const float*)d_in[0];
    const float* topW      = (const float*)d_in[1];
    const float* botW      = (const float*)d_in[2];
    const float* leftW     = (const float*)d_in[3];
    const float* rightW    = (const float*)d_in[4];
    const float* topleftW  = (const float*)d_in[5];
    const float* toprightW = (const float*)d_in[6];
    const float* botleftW  = (const float*)d_in[7];
    const float* botrightW = (const float*)d_in[8];
    const int*   num_patches = (const int*)d_in[10];

    const int C = in_sizes[1];                   // 128
    const int planes = in_sizes[0] / PLANE_IN;   // b * C = 16384

    weight_pad2d_kernel<<<planes, 256>>>(
        x, topW, botW, leftW, rightW,
        topleftW, toprightW, botleftW, botrightW,
        num_patches, C, (float*)d_out);
}

// round 4
// speedup vs baseline: 1.7385x; 1.0708x over previous
#include <cuda_runtime.h>
#include <cstdint>

#define Hh 56
#define Ww 56
#define HO 58
#define WO 58
#define PLANE_IN  3136   // 56*56
#define PLANE_OUT 3364   // 58*58

__global__ void __launch_bounds__(256, 8)
weight_pad2d_kernel(const float* __restrict__ x,
                    const float* __restrict__ topW,
                    const float* __restrict__ botW,
                    const float* __restrict__ leftW,
                    const float* __restrict__ rightW,
                    const float* __restrict__ topleftW,
                    const float* __restrict__ toprightW,
                    const float* __restrict__ botleftW,
                    const float* __restrict__ botrightW,
                    const int* __restrict__ num_patches_ptr,
                    int C, int planes,
                    float* __restrict__ out)
{
    const int tid  = threadIdx.x;
    const int warp = tid >> 5;           // 0..7
    const int lane = tid & 31;

    const int P  = *num_patches_ptr;
    const int PP = P * P;

    const bool ld = (lane < 28);   // lanes 0..27 load (56 floats)
    const bool st = (lane < 29);   // lanes 0..28 store (58 floats)

    for (int plane = blockIdx.x; plane < planes; plane += gridDim.x) {
        const int bidx  = plane / C;
        const int ch    = plane - bidx * C;

        const int within = bidx % PP;
        const bool topz   = within < P;
        const bool botz   = within >= PP - P;
        const bool leftz  = (bidx % P) == 0;
        const bool rightz = (bidx % P) == (P - 1);

        const float* __restrict__ xp = x   + (size_t)plane * PLANE_IN;
        float*       __restrict__ op = out + (size_t)plane * PLANE_OUT;

        // ---- peeled top row (r=0): warps 0,1 scalar ----
        if (tid < 64) {
            const int c = tid;
            if (c < WO) {
                float v;
                if (c == 0) {
                    v = (topz || leftz) ? 0.0f : topleftW[ch] * xp[0];
                } else if (c == WO - 1) {
                    v = (topz || rightz) ? 0.0f : toprightW[ch] * xp[Ww - 1];
                } else {
                    v = topz ? 0.0f : topW[ch] * (xp[c - 1] + xp[Ww + c - 1]);
                }
                op[c] = v;
            }
        } else if (tid < 128) {
            // ---- peeled bottom row (r=57): warps 2,3 scalar ----
            const int c = tid - 64;
            if (c < WO) {
                const float* x54 = xp + (Hh - 2) * Ww;
                const float* x55 = xp + (Hh - 1) * Ww;
                float v;
                if (c == 0) {
                    v = (botz || leftz) ? 0.0f : botleftW[ch] * x55[0];
                } else if (c == WO - 1) {
                    v = (botz || rightz) ? 0.0f : botrightW[ch] * x55[Ww - 1];
                } else {
                    v = botz ? 0.0f : botW[ch] * (x54[c - 1] + x55[c - 1]);
                }
                op[(HO - 1) * WO + c] = v;
            }
        }

        // ---- interior rows r = 1..56: one warp per row, float2, batched loads ----
        const float wLr = leftz  ? 0.0f : leftW[ch];
        const float wRr = rightz ? 0.0f : rightW[ch];

        // Phase 1: issue all 7 loads (MLP = 7)
        float2 g[7];
        #pragma unroll
        for (int k = 0; k < 7; k++) {
            const int ir = warp + 8 * k;          // input row = r-1
            g[k] = make_float2(0.0f, 0.0f);
            if (ld) g[k] = *(const float2*)(xp + ir * Ww + 2 * lane);
        }

        // Phase 2: shuffle + select + store
        #pragma unroll
        for (int k = 0; k < 7; k++) {
            const int r = 1 + warp + 8 * k;
            const float upx = __shfl_up_sync(0xffffffffu, g[k].x, 1);
            const float upy = __shfl_up_sync(0xffffffffu, g[k].y, 1);
            if (st) {
                const float o_lo = (lane == 0)  ? wLr * (g[k].x + g[k].y) : upy;
                const float o_hi = (lane == 28) ? wRr * (upx + upy)       : g[k].x;
                *(float2*)(op + r * WO + 2 * lane) = make_float2(o_lo, o_hi);
            }
        }
    }
}

extern "C" void kernel_launch(void* const* d_in, const int* in_sizes, int n_in,
                              void* d_out, int out_size)
{
    const float* x         = (const float*)d_in[0];
    const float* topW      = (const float*)d_in[1];
    const float* botW      = (const float*)d_in[2];
    const float* leftW     = (const float*)d_in[3];
    const float* rightW    = (const float*)d_in[4];
    const float* topleftW  = (const float*)d_in[5];
    const float* toprightW = (const float*)d_in[6];
    const float* botleftW  = (const float*)d_in[7];
    const float* botrightW = (const float*)d_in[8];
    const int*   num_patches = (const int*)d_in[10];

    const int C = in_sizes[1];                   // 128
    const int planes = in_sizes[0] / PLANE_IN;   // b * C = 16384

    // One full wave of persistent blocks: 148 SMs x 8 blocks of 256 threads
    int grid = 148 * 8;
    if (grid > planes) grid = planes;

    weight_pad2d_kernel<<<grid, 256>>>(
        x, topW, botW, leftW, rightW,
        topleftW, toprightW, botleftW, botrightW,
        num_patches, C, planes, (float*)d_out);
}